// round 12
// baseline (speedup 1.0000x reference)
#include <cuda_runtime.h>

#define NN 100000
#define EE 1000000
#define DD 64
#define NB_SCAN 196   // ceil(100000/512)

// ---------------- scratch (no allocs allowed) ----------------
__device__ __align__(256) float g_h[NN * DD];   // transformed features
__device__ __align__(256) float g_a[NN * DD];   // layer-1 output
__device__ int   g_deg[NN];                     // out-degree (src), memset 0; +1 = self loop
__device__ int   g_cnt[NN];                     // in-degree (dst), memset 0
__device__ int   g_cur[NN];                     // scatter cursors (= rowptr copy)
__device__ int   g_rowptr[NN + 1];
__device__ unsigned long long g_tile[NB_SCAN];  // lookback states, memset 0
__device__ float g_dis[NN];                     // rsqrt(deg+1)
__device__ float g_comb1[18 * DD];              // ebond[t]+edir[d]
__device__ float g_comb2[18 * DD];
__device__ uint2 g_rec[EE];                     // {src | combIdx<<17, norm}

// ---------------- small helpers ----------------
__device__ __forceinline__ unsigned long long fma2(unsigned long long a,
                                                   unsigned long long b,
                                                   unsigned long long c) {
    unsigned long long d;
    asm("fma.rn.f32x2 %0, %1, %2, %3;" : "=l"(d) : "l"(a), "l"(b), "l"(c));
    return d;
}
__device__ __forceinline__ unsigned long long packf2(float lo, float hi) {
    unsigned long long d;
    asm("mov.b64 %0, {%1, %2};" : "=l"(d) : "f"(lo), "f"(hi));
    return d;
}

// ---------------- GEMM body: Y[n][j] = sum_k act(X[n][k]) * W[j][k] + B[j] ----------
// f32x2-packed accumulators (row pairs). Thread (q, rb): cols {q+16jj}, rows rb*4..+3.
// W in smem as duplicated pairs {w,w}, column-swizzled (j&48)|((j+k)&15): LDS.64
// conflict-free. Dynamic smem: 32768 (Wd) + 17408 (xs) = 50176.
__device__ __forceinline__ void gemm_body(
    const float* __restrict__ X, const float* __restrict__ W,
    const float* __restrict__ Bv, float* __restrict__ Y, int N, int relu, int blk) {
    extern __shared__ char smem[];
    unsigned long long* Wd = (unsigned long long*)smem;          // [64][64] f32x2
    float(*xs)[68] = (float(*)[68])(smem + 32768);               // [64][68]
    int tid = threadIdx.x;

    for (int i = tid; i < 4096; i += 256) {
        int k = i & 63, j = i >> 6;
        float w = W[j * 64 + k];                                 // coalesced over k
        Wd[k * 64 + ((j & 48) | ((j + k) & 15))] = packf2(w, w);
    }
    int row0 = blk * 64;
    for (int i = tid; i < 1024; i += 256) {
        int r = i >> 4, c = i & 15;
        int row = row0 + r;
        float4 v = make_float4(0.f, 0.f, 0.f, 0.f);
        if (row < N) v = ((const float4*)(X + (size_t)row * DD))[c];
        if (relu) {
            v.x = fmaxf(v.x, 0.f); v.y = fmaxf(v.y, 0.f);
            v.z = fmaxf(v.z, 0.f); v.w = fmaxf(v.w, 0.f);
        }
        *(float4*)&xs[r][c * 4] = v;
    }
    __syncthreads();

    int q = tid & 15, rb = tid >> 4;
    int r0 = rb * 4;
    unsigned long long acc[2][4];
#pragma unroll
    for (int jj = 0; jj < 4; jj++) {
        float bj = Bv[q + 16 * jj];
        unsigned long long bb = packf2(bj, bj);
        acc[0][jj] = bb;
        acc[1][jj] = bb;
    }

#pragma unroll 16
    for (int k = 0; k < 64; k++) {
        const unsigned long long* wk = Wd + k * 64 + ((q + k) & 15);
        unsigned long long xp0 = packf2(xs[r0][k], xs[r0 + 1][k]);
        unsigned long long xp1 = packf2(xs[r0 + 2][k], xs[r0 + 3][k]);
#pragma unroll
        for (int jj = 0; jj < 4; jj++) {
            unsigned long long w = wk[16 * jj];
            acc[0][jj] = fma2(xp0, w, acc[0][jj]);
            acc[1][jj] = fma2(xp1, w, acc[1][jj]);
        }
    }

#pragma unroll
    for (int p = 0; p < 2; p++) {
#pragma unroll
        for (int rr = 0; rr < 2; rr++) {
            int row = row0 + r0 + 2 * p + rr;
            if (row < N) {
#pragma unroll
                for (int jj = 0; jj < 4; jj++) {
                    union { unsigned long long u; float2 f; } cv;
                    cv.u = acc[p][jj];
                    Y[(size_t)row * DD + q + 16 * jj] = rr ? cv.f.y : cv.f.x;
                }
            }
        }
    }
}

// ---------------- L1: GEMM blocks + histogram blocks + comb blocks ----------------
__global__ __launch_bounds__(256) void k_gemm_hist(
    const float* __restrict__ X, const float* __restrict__ W,
    const float* __restrict__ Bv, float* __restrict__ Y, int N, int relu,
    const int* __restrict__ src, const int* __restrict__ dst,
    int* __restrict__ deg, int* __restrict__ cnt, int E, int gemmBlocks,
    int histBlocks,
    const float* __restrict__ eb1, const float* __restrict__ ed1,
    const float* __restrict__ eb2, const float* __restrict__ ed2,
    float* __restrict__ c1, float* __restrict__ c2) {
    int b = blockIdx.x;
    if (b < gemmBlocks) {
        gemm_body(X, W, Bv, Y, N, relu, b);
    } else if (b < gemmBlocks + histBlocks) {
        int idx = (b - gemmBlocks) * 256 + threadIdx.x;
        int stride = histBlocks * 256;
        for (int e = idx; e < E; e += stride) {
            atomicAdd(&deg[src[e]], 1);
            atomicAdd(&cnt[dst[e]], 1);
        }
    } else {
        int r = b - gemmBlocks - histBlocks;   // 0..35
        int j = threadIdx.x;
        if (j < DD) {
            if (r < 18)
                c1[r * DD + j] = eb1[(r / 3) * DD + j] + ed1[(r % 3) * DD + j];
            else {
                int r2 = r - 18;
                c2[r2 * DD + j] = eb2[(r2 / 3) * DD + j] + ed2[(r2 % 3) * DD + j];
            }
        }
    }
}

// ---------------- L2: single-pass decoupled-lookback scan + dis ----------------
// rowptr[i] = exclusive prefix of cnt; cur[i] = rowptr[i]; dis[i] = rsqrt(deg[i]+1).
// tile[b] packed: flag in bits[63:62] (0=invalid, 1=aggregate, 2=inclusive prefix).
__global__ __launch_bounds__(512) void k_scan(
    const int* __restrict__ cnt, const int* __restrict__ deg,
    int* __restrict__ rowptr, int* __restrict__ cur, float* __restrict__ dis,
    unsigned long long* __restrict__ tile, int N, int E) {
    __shared__ int swarp[16];
    __shared__ int s_prefix;
    int b = blockIdx.x, t = threadIdx.x;
    int lane = t & 31, w = t >> 5;
    int i = b * 512 + t;
    int v = (i < N) ? cnt[i] : 0;

    // warp-inclusive scan
    int xi = v;
#pragma unroll
    for (int o = 1; o < 32; o <<= 1) {
        int y = __shfl_up_sync(0xFFFFFFFFu, xi, o);
        if (lane >= o) xi += y;
    }
    if (lane == 31) swarp[w] = xi;
    __syncthreads();
    if (t < 16) {
        int y = swarp[t];
#pragma unroll
        for (int o = 1; o < 16; o <<= 1) {
            int z = __shfl_up_sync(0xFFFFu, y, o);
            if (t >= o) y += z;
        }
        swarp[t] = y;
    }
    __syncthreads();
    int incl = xi + (w ? swarp[w - 1] : 0);
    int total = swarp[15];

    if (t == 0) {
        if (b == 0) {
            __threadfence();
            atomicExch(&tile[0], (2ULL << 62) | (unsigned long long)total);
            s_prefix = 0;
        } else {
            __threadfence();
            atomicExch(&tile[b], (1ULL << 62) | (unsigned long long)total);
            long long sum = 0;
            int j = b - 1;
            while (true) {
                unsigned long long s = atomicAdd(&tile[j], 0ULL);
                unsigned f = (unsigned)(s >> 62);
                if (f == 0) continue;
                sum += (long long)(s & 0x3FFFFFFFFFFFFFFFULL);
                if (f == 2u) break;
                j--;
            }
            s_prefix = (int)sum;
            __threadfence();
            atomicExch(&tile[b], (2ULL << 62) | (unsigned long long)(sum + total));
        }
    }
    __syncthreads();
    int excl = incl - v + s_prefix;
    if (i < N) {
        rowptr[i] = excl;
        cur[i] = excl;
        dis[i] = rsqrtf((float)(deg[i] + 1));   // +1 = self loop
    }
    if (b == 0 && t == 0) rowptr[N] = E;
}

// ---------------- L3: scatter packed edge records into CSR slots ----------------
__global__ void k_scatter(const int* __restrict__ src, const int* __restrict__ dst,
                          const int* __restrict__ attr, const float* __restrict__ dis,
                          int* __restrict__ cur, uint2* __restrict__ rec, int E) {
    int e = blockIdx.x * blockDim.x + threadIdx.x;
    if (e >= E) return;
    int d = dst[e];
    int s = src[e];
    int2 at = ((const int2*)attr)[e];
    float nm = __ldg(dis + s) * __ldg(dis + d);
    int pos = atomicAdd(&cur[d], 1);
    rec[pos] = make_uint2((unsigned)s | ((unsigned)(at.x * 3 + at.y) << 17),
                          __float_as_uint(nm));
}

// ---------------- L4/L6: CSR aggregation, 4 edges/iter, fused self-loop ----------
// out[v] = dis[v]^2*(h[v]+comb[12]) + sum_{e in CSR[v]} norm_e*(h[src_e]+comb[c_e])
__global__ __launch_bounds__(256) void k_agg(
    const float* __restrict__ h, const float* __restrict__ dis,
    const float* __restrict__ comb, const int* __restrict__ rowptr,
    const uint2* __restrict__ rec, float* __restrict__ out, int N) {
    __shared__ float sc[18 * DD];
    for (int i = threadIdx.x; i < 18 * DD; i += 256) sc[i] = comb[i];
    __syncthreads();

    int t = blockIdx.x * 256 + threadIdx.x;
    int v = t >> 4, q = t & 15;
    if (v >= N) return;

    float dv = dis[v];
    float w = dv * dv;
    float4 hv = *(const float4*)(h + (size_t)v * DD + q * 4);
    float4 e = *(const float4*)(sc + 12 * DD + q * 4);
    float ax = w * (hv.x + e.x), ay = w * (hv.y + e.y);
    float az = w * (hv.z + e.z), aw = w * (hv.w + e.w);

    int i = rowptr[v], end = rowptr[v + 1];
    for (; i + 4 <= end; i += 4) {
        uint2 r0 = __ldg(&rec[i]);
        uint2 r1 = __ldg(&rec[i + 1]);
        uint2 r2 = __ldg(&rec[i + 2]);
        uint2 r3 = __ldg(&rec[i + 3]);
        float4 h0 = *(const float4*)(h + (size_t)(r0.x & 0x1FFFF) * DD + q * 4);
        float4 h1 = *(const float4*)(h + (size_t)(r1.x & 0x1FFFF) * DD + q * 4);
        float4 h2 = *(const float4*)(h + (size_t)(r2.x & 0x1FFFF) * DD + q * 4);
        float4 h3 = *(const float4*)(h + (size_t)(r3.x & 0x1FFFF) * DD + q * 4);
        float4 e0 = *(const float4*)(sc + (r0.x >> 17) * DD + q * 4);
        float4 e1 = *(const float4*)(sc + (r1.x >> 17) * DD + q * 4);
        float4 e2 = *(const float4*)(sc + (r2.x >> 17) * DD + q * 4);
        float4 e3 = *(const float4*)(sc + (r3.x >> 17) * DD + q * 4);
        float n0 = __uint_as_float(r0.y), n1 = __uint_as_float(r1.y);
        float n2 = __uint_as_float(r2.y), n3 = __uint_as_float(r3.y);
        ax += n0 * (h0.x + e0.x); ay += n0 * (h0.y + e0.y);
        az += n0 * (h0.z + e0.z); aw += n0 * (h0.w + e0.w);
        ax += n1 * (h1.x + e1.x); ay += n1 * (h1.y + e1.y);
        az += n1 * (h1.z + e1.z); aw += n1 * (h1.w + e1.w);
        ax += n2 * (h2.x + e2.x); ay += n2 * (h2.y + e2.y);
        az += n2 * (h2.z + e2.z); aw += n2 * (h2.w + e2.w);
        ax += n3 * (h3.x + e3.x); ay += n3 * (h3.y + e3.y);
        az += n3 * (h3.z + e3.z); aw += n3 * (h3.w + e3.w);
    }
    for (; i < end; i++) {
        uint2 r0 = __ldg(&rec[i]);
        float n0 = __uint_as_float(r0.y);
        float4 h0 = *(const float4*)(h + (size_t)(r0.x & 0x1FFFF) * DD + q * 4);
        float4 e0 = *(const float4*)(sc + (r0.x >> 17) * DD + q * 4);
        ax += n0 * (h0.x + e0.x); ay += n0 * (h0.y + e0.y);
        az += n0 * (h0.z + e0.z); aw += n0 * (h0.w + e0.w);
    }
    *(float4*)(out + (size_t)v * DD + q * 4) = make_float4(ax, ay, az, aw);
}

// ---------------- launch ----------------
extern "C" void kernel_launch(void* const* d_in, const int* in_sizes, int n_in,
                              void* d_out, int out_size) {
    const float* x   = (const float*)d_in[0];
    const int*   ei  = (const int*)d_in[1];
    const int*   ea  = (const int*)d_in[2];
    const float* W1  = (const float*)d_in[3];
    const float* b1  = (const float*)d_in[4];
    const float* eb1 = (const float*)d_in[5];
    const float* ed1 = (const float*)d_in[6];
    const float* W2  = (const float*)d_in[7];
    const float* b2  = (const float*)d_in[8];
    const float* eb2 = (const float*)d_in[9];
    const float* ed2 = (const float*)d_in[10];

    int N = in_sizes[0] / DD;   // 100000
    int E = in_sizes[1] / 2;    // 1000000
    const int* src = ei;
    const int* dst = ei + E;

    float *h, *a, *dis, *c1, *c2;
    int *deg, *cnt, *cur, *rowptr;
    unsigned long long* tile;
    uint2* rec;
    cudaGetSymbolAddress((void**)&h, g_h);
    cudaGetSymbolAddress((void**)&a, g_a);
    cudaGetSymbolAddress((void**)&deg, g_deg);
    cudaGetSymbolAddress((void**)&cnt, g_cnt);
    cudaGetSymbolAddress((void**)&cur, g_cur);
    cudaGetSymbolAddress((void**)&rowptr, g_rowptr);
    cudaGetSymbolAddress((void**)&tile, g_tile);
    cudaGetSymbolAddress((void**)&dis, g_dis);
    cudaGetSymbolAddress((void**)&c1, g_comb1);
    cudaGetSymbolAddress((void**)&c2, g_comb2);
    cudaGetSymbolAddress((void**)&rec, g_rec);
    float* out = (float*)d_out;

    const int B = 256;
    int gE  = (E + B - 1) / B;
    int gNv = (N * 16 + B - 1) / B;
    int gG  = (N + 63) / 64;            // gemm blocks
    int NB  = (N + 511) / 512;          // scan blocks (== NB_SCAN)
    const int HB = 1024;                // hist blocks riding alongside GEMM1

    const int GEMM_SMEM = 32768 + 64 * 68 * 4;  // 50176
    cudaFuncSetAttribute(k_gemm_hist, cudaFuncAttributeMaxDynamicSharedMemorySize,
                         GEMM_SMEM);

    // resets (memset nodes, not kernel launches)
    cudaMemsetAsync(deg, 0, (size_t)N * sizeof(int));
    cudaMemsetAsync(cnt, 0, (size_t)N * sizeof(int));
    cudaMemsetAsync(tile, 0, (size_t)NB * sizeof(unsigned long long));

    // L1: GEMM layer 1 + degree histogram + comb tables
    k_gemm_hist<<<gG + HB + 36, B, GEMM_SMEM>>>(x, W1, b1, h, N, 0,
                                                src, dst, deg, cnt, E, gG, HB,
                                                eb1, ed1, eb2, ed2, c1, c2);
    // L2: single-pass scan -> rowptr, cursors, dis
    k_scan<<<NB, 512>>>(cnt, deg, rowptr, cur, dis, tile, N, E);
    // L3: scatter edge records
    k_scatter<<<gE, B>>>(src, dst, ea, dis, cur, rec, E);
    // L4: layer-1 aggregation (4th launch -> ncu capture)
    k_agg<<<gNv, B>>>(h, dis, c1, rowptr, rec, a, N);
    // L5: GEMM layer 2 (ReLU fused into input load)
    k_gemm_hist<<<gG, B, GEMM_SMEM>>>(a, W2, b2, h, N, 1,
                                      src, dst, deg, cnt, 0, gG, 0,
                                      eb1, ed1, eb2, ed2, c1, c2);
    // L6: layer-2 aggregation -> output
    k_agg<<<gNv, B>>>(h, dis, c2, rowptr, rec, out, N);
}

// round 16
// speedup vs baseline: 1.0841x; 1.0841x over previous
#include <cuda_runtime.h>

#define NN 100000
#define EE 1000000
#define DD 64

// ---------------- scratch (no allocs allowed) ----------------
__device__ __align__(256) float g_h[NN * DD];   // layer-1 transformed features
__device__ __align__(256) float g_a[NN * DD];   // fused agg1+gemm2 output
__device__ int   g_deg[NN];                     // out-degree (src), memset 0 (+1 = self loop)
__device__ int   g_cnt[NN];                     // in-degree (dst), memset 0
__device__ int   g_cur[NN];                     // scatter cursors (= rowptr copy)
__device__ int   g_excl[NN];                    // block-local exclusive scan
__device__ int   g_rowptr[NN + 1];
__device__ int   g_bsum[512];
__device__ float g_dis[NN];                     // rsqrt(deg+1)
__device__ float g_comb1[18 * DD];              // ebond[t]+edir[d]
__device__ float g_comb2[18 * DD];
__device__ uint2 g_rec[EE];                     // {src<<8 | combIdx, norm}

// ---------------- small helpers ----------------
__device__ __forceinline__ unsigned long long fma2(unsigned long long a,
                                                   unsigned long long b,
                                                   unsigned long long c) {
    unsigned long long d;
    asm("fma.rn.f32x2 %0, %1, %2, %3;" : "=l"(d) : "l"(a), "l"(b), "l"(c));
    return d;
}
__device__ __forceinline__ unsigned long long packf2(float lo, float hi) {
    unsigned long long d;
    asm("mov.b64 %0, {%1, %2};" : "=l"(d) : "f"(lo), "f"(hi));
    return d;
}

// ---------------- shared agg-per-node body ----------------
// returns column-slice q (4 floats) of:
// dis[v]^2*(h[v]+comb[12]) + sum_e norm_e*(h[src_e]+comb[c_e])
__device__ __forceinline__ float4 agg_node(
    int v, int q, const float* __restrict__ h, const float* __restrict__ dis,
    const float* __restrict__ sc, const int* __restrict__ rowptr,
    const uint2* __restrict__ rec) {
    const char* hb = (const char*)h;
    const char* sb = (const char*)sc;
    int qb = q << 4;

    float dv = dis[v];
    float w = dv * dv;
    float4 hv = *(const float4*)(hb + ((size_t)v << 8) + qb);
    float4 e = *(const float4*)(sb + 12 * 256 + qb);
    float ax = w * (hv.x + e.x), ay = w * (hv.y + e.y);
    float az = w * (hv.z + e.z), aw = w * (hv.w + e.w);

    int i = rowptr[v], end = rowptr[v + 1];
    for (; i + 4 <= end; i += 4) {
        uint2 r0 = __ldg(&rec[i]);
        uint2 r1 = __ldg(&rec[i + 1]);
        uint2 r2 = __ldg(&rec[i + 2]);
        uint2 r3 = __ldg(&rec[i + 3]);
        float4 h0 = *(const float4*)(hb + (r0.x & 0xFFFFFF00u) + qb);
        float4 h1 = *(const float4*)(hb + (r1.x & 0xFFFFFF00u) + qb);
        float4 h2 = *(const float4*)(hb + (r2.x & 0xFFFFFF00u) + qb);
        float4 h3 = *(const float4*)(hb + (r3.x & 0xFFFFFF00u) + qb);
        float4 e0 = *(const float4*)(sb + ((r0.x & 0xFFu) << 8) + qb);
        float4 e1 = *(const float4*)(sb + ((r1.x & 0xFFu) << 8) + qb);
        float4 e2 = *(const float4*)(sb + ((r2.x & 0xFFu) << 8) + qb);
        float4 e3 = *(const float4*)(sb + ((r3.x & 0xFFu) << 8) + qb);
        float n0 = __uint_as_float(r0.y), n1 = __uint_as_float(r1.y);
        float n2 = __uint_as_float(r2.y), n3 = __uint_as_float(r3.y);
        ax += n0 * (h0.x + e0.x); ay += n0 * (h0.y + e0.y);
        az += n0 * (h0.z + e0.z); aw += n0 * (h0.w + e0.w);
        ax += n1 * (h1.x + e1.x); ay += n1 * (h1.y + e1.y);
        az += n1 * (h1.z + e1.z); aw += n1 * (h1.w + e1.w);
        ax += n2 * (h2.x + e2.x); ay += n2 * (h2.y + e2.y);
        az += n2 * (h2.z + e2.z); aw += n2 * (h2.w + e2.w);
        ax += n3 * (h3.x + e3.x); ay += n3 * (h3.y + e3.y);
        az += n3 * (h3.z + e3.z); aw += n3 * (h3.w + e3.w);
    }
    for (; i < end; i++) {
        uint2 r0 = __ldg(&rec[i]);
        float n0 = __uint_as_float(r0.y);
        float4 h0 = *(const float4*)(hb + (r0.x & 0xFFFFFF00u) + qb);
        float4 e0 = *(const float4*)(sb + ((r0.x & 0xFFu) << 8) + qb);
        ax += n0 * (h0.x + e0.x); ay += n0 * (h0.y + e0.y);
        az += n0 * (h0.z + e0.z); aw += n0 * (h0.w + e0.w);
    }
    return make_float4(ax, ay, az, aw);
}

// ---------------- GEMM body (reads X from global) ----------------
// f32x2-packed accumulators; W duplicated {w,w}, col-swizzled (j&48)|((j+k)&15).
__device__ __forceinline__ void gemm_body(
    const float* __restrict__ X, const float* __restrict__ W,
    const float* __restrict__ Bv, float* __restrict__ Y, int N, int blk) {
    extern __shared__ char smem[];
    unsigned long long* Wd = (unsigned long long*)smem;          // [64][64] f32x2
    float(*xs)[68] = (float(*)[68])(smem + 32768);               // [64][68]
    int tid = threadIdx.x;

    for (int i = tid; i < 4096; i += 256) {
        int k = i & 63, j = i >> 6;
        float w = W[j * 64 + k];
        Wd[k * 64 + ((j & 48) | ((j + k) & 15))] = packf2(w, w);
    }
    int row0 = blk * 64;
    for (int i = tid; i < 1024; i += 256) {
        int r = i >> 4, c = i & 15;
        int row = row0 + r;
        float4 v = make_float4(0.f, 0.f, 0.f, 0.f);
        if (row < N) v = ((const float4*)(X + (size_t)row * DD))[c];
        *(float4*)&xs[r][c * 4] = v;
    }
    __syncthreads();

    int q = tid & 15, rb = tid >> 4;
    int r0 = rb * 4;
    unsigned long long acc[2][4];
#pragma unroll
    for (int jj = 0; jj < 4; jj++) {
        float bj = Bv[q + 16 * jj];
        unsigned long long bb = packf2(bj, bj);
        acc[0][jj] = bb; acc[1][jj] = bb;
    }
#pragma unroll 16
    for (int k = 0; k < 64; k++) {
        const unsigned long long* wk = Wd + k * 64 + ((q + k) & 15);
        unsigned long long xp0 = packf2(xs[r0][k], xs[r0 + 1][k]);
        unsigned long long xp1 = packf2(xs[r0 + 2][k], xs[r0 + 3][k]);
#pragma unroll
        for (int jj = 0; jj < 4; jj++) {
            unsigned long long w = wk[16 * jj];
            acc[0][jj] = fma2(xp0, w, acc[0][jj]);
            acc[1][jj] = fma2(xp1, w, acc[1][jj]);
        }
    }
#pragma unroll
    for (int p = 0; p < 2; p++)
#pragma unroll
        for (int rr = 0; rr < 2; rr++) {
            int row = row0 + r0 + 2 * p + rr;
            if (row < N)
#pragma unroll
                for (int jj = 0; jj < 4; jj++) {
                    union { unsigned long long u; float2 f; } cv;
                    cv.u = acc[p][jj];
                    Y[(size_t)row * DD + q + 16 * jj] = rr ? cv.f.y : cv.f.x;
                }
        }
}

// ---------------- L1: GEMM1 blocks + histogram blocks + comb blocks ----------------
__global__ __launch_bounds__(256) void k_gemm_hist(
    const float* __restrict__ X, const float* __restrict__ W,
    const float* __restrict__ Bv, float* __restrict__ Y, int N,
    const int* __restrict__ src, const int* __restrict__ dst,
    int* __restrict__ deg, int* __restrict__ cnt, int E, int gemmBlocks,
    int histBlocks,
    const float* __restrict__ eb1, const float* __restrict__ ed1,
    const float* __restrict__ eb2, const float* __restrict__ ed2,
    float* __restrict__ c1, float* __restrict__ c2) {
    int b = blockIdx.x;
    if (b < gemmBlocks) {
        gemm_body(X, W, Bv, Y, N, b);
    } else if (b < gemmBlocks + histBlocks) {
        int idx = (b - gemmBlocks) * 256 + threadIdx.x;
        int stride = histBlocks * 256;
        for (int e = idx; e < E; e += stride) {
            atomicAdd(&deg[src[e]], 1);
            atomicAdd(&cnt[dst[e]], 1);
        }
    } else {
        int r = b - gemmBlocks - histBlocks;   // 0..35
        int j = threadIdx.x;
        if (j < DD) {
            if (r < 18)
                c1[r * DD + j] = eb1[(r / 3) * DD + j] + ed1[(r % 3) * DD + j];
            else {
                int r2 = r - 18;
                c2[r2 * DD + j] = eb2[(r2 / 3) * DD + j] + ed2[(r2 % 3) * DD + j];
            }
        }
    }
}

// ---------------- L2: block-local scan of cnt + dis = rsqrt(deg+1) ----------------
__global__ void k_scan1_dis(const int* __restrict__ cnt, const int* __restrict__ deg,
                            int* __restrict__ excl, int* __restrict__ bsum,
                            float* __restrict__ dis, int N) {
    __shared__ int s[512];
    int tid = threadIdx.x;
    int i = blockIdx.x * 512 + tid;
    int v = (i < N) ? cnt[i] : 0;
    s[tid] = v;
    __syncthreads();
    for (int off = 1; off < 512; off <<= 1) {
        int t = (tid >= off) ? s[tid - off] : 0;
        __syncthreads();
        s[tid] += t;
        __syncthreads();
    }
    if (i < N) {
        excl[i] = s[tid] - v;
        dis[i] = rsqrtf((float)(deg[i] + 1));
    }
    if (tid == 511) bsum[blockIdx.x] = s[511];
}

// ---------------- L3: per-block prefix of bsum + final rowptr + cursor copy -------
__global__ void k_scan23(const int* __restrict__ excl, const int* __restrict__ bsum,
                         int* __restrict__ rowptr, int* __restrict__ cur,
                         int N, int E, int NB) {
    __shared__ int warpsum[16];
    __shared__ int prefix_s;
    int b = blockIdx.x, t = threadIdx.x;
    int v = (t < b && t < NB) ? bsum[t] : 0;
#pragma unroll
    for (int o = 16; o; o >>= 1) v += __shfl_down_sync(0xFFFFFFFFu, v, o);
    if ((t & 31) == 0) warpsum[t >> 5] = v;
    __syncthreads();
    if (t == 0) {
        int s = 0;
#pragma unroll
        for (int w = 0; w < 16; w++) s += warpsum[w];
        prefix_s = s;
    }
    __syncthreads();
    int prefix = prefix_s;
    int i = b * 512 + t;
    if (i < N) {
        int r = excl[i] + prefix;
        rowptr[i] = r;
        cur[i] = r;
    }
    if (b == 0 && t == 0) rowptr[N] = E;
}

// ---------------- L4: scatter packed edge records into CSR slots ----------------
__global__ void k_scatter(const int* __restrict__ src, const int* __restrict__ dst,
                          const int* __restrict__ attr, const float* __restrict__ dis,
                          int* __restrict__ cur, uint2* __restrict__ rec, int E) {
    int e = blockIdx.x * blockDim.x + threadIdx.x;
    if (e >= E) return;
    int d = dst[e];
    int s = src[e];
    int2 at = ((const int2*)attr)[e];
    float nm = __ldg(dis + s) * __ldg(dis + d);
    int pos = atomicAdd(&cur[d], 1);
    rec[pos] = make_uint2(((unsigned)s << 8) | (unsigned)(at.x * 3 + at.y),
                          __float_as_uint(nm));
}

// ---------------- L5: fused layer-1 aggregation + layer-2 GEMM ----------------
// Each block: agg 64 nodes (reads h) -> relu -> xs (smem), then GEMM tile -> Y (g_a).
// NOTE: Y must NOT alias h — all blocks gather arbitrary h rows concurrently.
// Dynamic smem: Wd 32768 + xs 17408 + sc 4608 = 54784.
__global__ __launch_bounds__(256) void k_agg_gemm(
    const float* __restrict__ h, const float* __restrict__ dis,
    const float* __restrict__ comb, const int* __restrict__ rowptr,
    const uint2* __restrict__ rec,
    const float* __restrict__ W, const float* __restrict__ Bv,
    float* __restrict__ Y, int N) {
    extern __shared__ char smem[];
    unsigned long long* Wd = (unsigned long long*)smem;          // [64][64] f32x2
    float(*xs)[68] = (float(*)[68])(smem + 32768);               // [64][68]
    float* sc = (float*)(smem + 32768 + 17408);                  // [18*64]
    int tid = threadIdx.x;

    for (int i = tid; i < 4096; i += 256) {
        int k = i & 63, j = i >> 6;
        float w = W[j * 64 + k];
        Wd[k * 64 + ((j & 48) | ((j + k) & 15))] = packf2(w, w);
    }
    for (int i = tid; i < 18 * DD; i += 256) sc[i] = comb[i];
    __syncthreads();

    int row0 = blockIdx.x * 64;
    int q = tid & 15;
#pragma unroll
    for (int it = 0; it < 4; it++) {
        int r = it * 16 + (tid >> 4);
        int v = row0 + r;
        float4 o = make_float4(0.f, 0.f, 0.f, 0.f);
        if (v < N) {
            o = agg_node(v, q, h, dis, sc, rowptr, rec);
            o.x = fmaxf(o.x, 0.f); o.y = fmaxf(o.y, 0.f);
            o.z = fmaxf(o.z, 0.f); o.w = fmaxf(o.w, 0.f);
        }
        *(float4*)&xs[r][q * 4] = o;
    }
    __syncthreads();

    int rb = tid >> 4;
    int r0 = rb * 4;
    unsigned long long acc[2][4];
#pragma unroll
    for (int jj = 0; jj < 4; jj++) {
        float bj = Bv[q + 16 * jj];
        unsigned long long bb = packf2(bj, bj);
        acc[0][jj] = bb; acc[1][jj] = bb;
    }
#pragma unroll 16
    for (int k = 0; k < 64; k++) {
        const unsigned long long* wk = Wd + k * 64 + ((q + k) & 15);
        unsigned long long xp0 = packf2(xs[r0][k], xs[r0 + 1][k]);
        unsigned long long xp1 = packf2(xs[r0 + 2][k], xs[r0 + 3][k]);
#pragma unroll
        for (int jj = 0; jj < 4; jj++) {
            unsigned long long w = wk[16 * jj];
            acc[0][jj] = fma2(xp0, w, acc[0][jj]);
            acc[1][jj] = fma2(xp1, w, acc[1][jj]);
        }
    }
#pragma unroll
    for (int p = 0; p < 2; p++)
#pragma unroll
        for (int rr = 0; rr < 2; rr++) {
            int row = row0 + r0 + 2 * p + rr;
            if (row < N)
#pragma unroll
                for (int jj = 0; jj < 4; jj++) {
                    union { unsigned long long u; float2 f; } cv;
                    cv.u = acc[p][jj];
                    Y[(size_t)row * DD + q + 16 * jj] = rr ? cv.f.y : cv.f.x;
                }
        }
}

// ---------------- L6: layer-2 aggregation -> output ----------------
__global__ __launch_bounds__(256) void k_agg(
    const float* __restrict__ h, const float* __restrict__ dis,
    const float* __restrict__ comb, const int* __restrict__ rowptr,
    const uint2* __restrict__ rec, float* __restrict__ out, int N) {
    __shared__ float sc[18 * DD];
    for (int i = threadIdx.x; i < 18 * DD; i += 256) sc[i] = comb[i];
    __syncthreads();
    int t = blockIdx.x * 256 + threadIdx.x;
    int v = t >> 4, q = t & 15;
    if (v >= N) return;
    float4 o = agg_node(v, q, h, dis, sc, rowptr, rec);
    *(float4*)(out + (size_t)v * DD + q * 4) = o;
}

// ---------------- launch ----------------
extern "C" void kernel_launch(void* const* d_in, const int* in_sizes, int n_in,
                              void* d_out, int out_size) {
    const float* x   = (const float*)d_in[0];
    const int*   ei  = (const int*)d_in[1];
    const int*   ea  = (const int*)d_in[2];
    const float* W1  = (const float*)d_in[3];
    const float* b1  = (const float*)d_in[4];
    const float* eb1 = (const float*)d_in[5];
    const float* ed1 = (const float*)d_in[6];
    const float* W2  = (const float*)d_in[7];
    const float* b2  = (const float*)d_in[8];
    const float* eb2 = (const float*)d_in[9];
    const float* ed2 = (const float*)d_in[10];

    int N = in_sizes[0] / DD;   // 100000
    int E = in_sizes[1] / 2;    // 1000000
    const int* src = ei;
    const int* dst = ei + E;

    float *h, *a, *dis, *c1, *c2;
    int *deg, *cnt, *cur, *rowptr, *excl, *bsum;
    uint2* rec;
    cudaGetSymbolAddress((void**)&h, g_h);
    cudaGetSymbolAddress((void**)&a, g_a);
    cudaGetSymbolAddress((void**)&deg, g_deg);
    cudaGetSymbolAddress((void**)&cnt, g_cnt);
    cudaGetSymbolAddress((void**)&cur, g_cur);
    cudaGetSymbolAddress((void**)&rowptr, g_rowptr);
    cudaGetSymbolAddress((void**)&excl, g_excl);
    cudaGetSymbolAddress((void**)&bsum, g_bsum);
    cudaGetSymbolAddress((void**)&dis, g_dis);
    cudaGetSymbolAddress((void**)&c1, g_comb1);
    cudaGetSymbolAddress((void**)&c2, g_comb2);
    cudaGetSymbolAddress((void**)&rec, g_rec);
    float* out = (float*)d_out;

    const int B = 256;
    int gE  = (E + B - 1) / B;
    int gNv = (N * 16 + B - 1) / B;
    int gG  = (N + 63) / 64;            // gemm/fused blocks
    int NB  = (N + 511) / 512;          // scan blocks
    const int HB = 1024;                // hist blocks riding alongside GEMM1

    const int GEMM_SMEM  = 32768 + 64 * 68 * 4;          // 50176
    const int FUSED_SMEM = GEMM_SMEM + 18 * 64 * 4;      // 54784
    cudaFuncSetAttribute(k_gemm_hist, cudaFuncAttributeMaxDynamicSharedMemorySize,
                         GEMM_SMEM);
    cudaFuncSetAttribute(k_agg_gemm, cudaFuncAttributeMaxDynamicSharedMemorySize,
                         FUSED_SMEM);

    // resets (memset nodes, not kernel launches)
    cudaMemsetAsync(deg, 0, (size_t)N * sizeof(int));
    cudaMemsetAsync(cnt, 0, (size_t)N * sizeof(int));

    // L1: GEMM layer 1 + degree histogram + comb tables
    k_gemm_hist<<<gG + HB + 36, B, GEMM_SMEM>>>(x, W1, b1, h, N,
                                                src, dst, deg, cnt, E, gG, HB,
                                                eb1, ed1, eb2, ed2, c1, c2);
    // L2: block scan of cnt + dis
    k_scan1_dis<<<NB, 512>>>(cnt, deg, excl, bsum, dis, N);
    // L3: finalize rowptr + cursors
    k_scan23<<<NB, 512>>>(excl, bsum, rowptr, cur, N, E, NB);
    // L4: scatter edge records (ncu capture slot)
    k_scatter<<<gE, B>>>(src, dst, ea, dis, cur, rec, E);
    // L5: fused layer-1 aggregation + layer-2 GEMM -> g_a (no aliasing with h!)
    k_agg_gemm<<<gG, B, FUSED_SMEM>>>(h, dis, c1, rowptr, rec, W2, b2, a, N);
    // L6: layer-2 aggregation -> output
    k_agg<<<gNv, B>>>(a, dis, c2, rowptr, rec, out, N);
}